// round 13
// baseline (speedup 1.0000x reference)
#include <cuda_runtime.h>
#include <cuda_fp16.h>

#define NN    50000
#define NE    800000
#define ETOT  (NE + NN)       // edges + self loops
#define FOUT  256             // HEADS * HIDDEN
#define HID   64
#define NPAD  50176           // 196 * 256
#define NBLK  196

// ---------------- scratch (device globals; no allocation allowed) ----------
__device__ __half g_hh[NN * FOUT];     // per-layer node features, fp16 [N, H*C]
__device__ float  g_asrc[NN * 4];
__device__ float  g_adst[NN * 4];
__device__ float  g_feat1[NN * HID];
__device__ float  g_feat2[NN * HID];

// CSR build (dst-sorted edges; built once per call, reused by both layers)
// g_cnt starts zero (static init) and is re-zeroed by k_scan23 each call.
__device__ int g_cnt[NPAD];
__device__ int g_incl[NPAD];
__device__ int g_bsum[NBLK];
__device__ int g_row[NN + 1];
__device__ int g_cur[NN];
__device__ int g_es[ETOT];             // src node ids grouped by dst

// ---------------- CSR build ------------------------------------------------
__global__ void k_count(const int* __restrict__ ei) {
    int e = blockIdx.x * blockDim.x + threadIdx.x;
    if (e >= ETOT) return;
    int dst = (e < NE) ? ei[NE + e] : (e - NE);
    atomicAdd(&g_cnt[dst], 1);
}

__global__ void k_scan1() {
    __shared__ int s[256];
    int t = threadIdx.x, i = blockIdx.x * 256 + t;
    int c = g_cnt[i];
    s[t] = c;
    __syncthreads();
#pragma unroll
    for (int off = 1; off < 256; off <<= 1) {
        int v = (t >= off) ? s[t - off] : 0;
        __syncthreads();
        s[t] += v;
        __syncthreads();
    }
    g_incl[i] = s[t];
    if (t == 255) g_bsum[blockIdx.x] = s[255];
}

// merged scan2+scan3: each block computes its own prefix offset from g_bsum,
// then finalizes row/cur for its 256 nodes and re-zeroes g_cnt.
__global__ void k_scan23() {
    __shared__ int s[256];
    int t = threadIdx.x;
    int b = blockIdx.x;
    s[t] = (t < b) ? g_bsum[t] : 0;    // sum of block-sums before block b
    __syncthreads();
#pragma unroll
    for (int off = 128; off > 0; off >>= 1) {
        if (t < off) s[t] += s[t + off];
        __syncthreads();
    }
    int boff = s[0];
    int i = b * 256 + t;
    int inc = g_incl[i] + boff;
    int c = g_cnt[i];
    if (i < NN) {
        g_row[i + 1] = inc;
        g_cur[i] = inc - c;
    }
    g_cnt[i] = 0;                      // ready for next call (replay-invariant)
    if (i == 0) g_row[0] = 0;
}

__global__ void k_scatter(const int* __restrict__ ei) {
    int e = blockIdx.x * blockDim.x + threadIdx.x;
    if (e >= ETOT) return;
    int src, dst;
    if (e < NE) { src = ei[e]; dst = ei[NE + e]; }
    else        { src = dst = e - NE; }
    int pos = atomicAdd(&g_cur[dst], 1);
    g_es[pos] = src;
}

// ---------------- feature GEMM: g_hh = fp16(X @ W)  (W: [FIN, 256]) -------
template <int FIN>
__global__ void k_gemm(const float* __restrict__ X, const float* __restrict__ W) {
    extern __shared__ float sm[];
    float* Wsh = sm;                 // [FIN][256]
    float* Xs  = sm + FIN * FOUT;    // [FIN][8]
    int t = threadIdx.x;

    for (int i = t; i < FIN * (FOUT / 4); i += 256)
        ((float4*)Wsh)[i] = ((const float4*)W)[i];

    const int nTiles = (NN + 7) / 8;
    for (int tile = blockIdx.x; tile < nTiles; tile += gridDim.x) {
        int n0 = tile * 8;
        __syncthreads();
        for (int idx = t; idx < 8 * FIN; idx += 256) {
            int k = idx >> 3, i = idx & 7;
            int n = n0 + i;
            Xs[idx] = (n < NN) ? X[n * FIN + k] : 0.f;
        }
        __syncthreads();

        float acc[8];
#pragma unroll
        for (int i = 0; i < 8; i++) acc[i] = 0.f;
#pragma unroll
        for (int k = 0; k < FIN; k++) {
            float  w  = Wsh[k * FOUT + t];
            float4 xa = *(const float4*)&Xs[k * 8];
            float4 xb = *(const float4*)&Xs[k * 8 + 4];
            acc[0] = fmaf(xa.x, w, acc[0]);
            acc[1] = fmaf(xa.y, w, acc[1]);
            acc[2] = fmaf(xa.z, w, acc[2]);
            acc[3] = fmaf(xa.w, w, acc[3]);
            acc[4] = fmaf(xb.x, w, acc[4]);
            acc[5] = fmaf(xb.y, w, acc[5]);
            acc[6] = fmaf(xb.z, w, acc[6]);
            acc[7] = fmaf(xb.w, w, acc[7]);
        }
#pragma unroll
        for (int i = 0; i < 8; i++) {
            int n = n0 + i;
            if (n < NN) g_hh[n * FOUT + t] = __float2half_rn(acc[i]);
        }
    }
}

// ---------------- alpha_src / alpha_dst per (node, head) ------------------
__global__ void k_alpha(const float* __restrict__ a_src, const float* __restrict__ a_dst) {
    int i = blockIdx.x * blockDim.x + threadIdx.x;
    if (i >= NN * 4) return;
    int node = i >> 2, hd = i & 3;
    const __half2* hp = (const __half2*)&g_hh[node * FOUT + hd * HID];
    const float2*  ap = (const float2*)&a_src[hd * HID];
    const float2*  dp = (const float2*)&a_dst[hd * HID];
    float s = 0.f, d = 0.f;
#pragma unroll
    for (int j = 0; j < HID / 2; j++) {
        float2 h2 = __half22float2(hp[j]);
        float2 a2 = ap[j], d2 = dp[j];
        s += h2.x * a2.x + h2.y * a2.y;
        d += h2.x * d2.x + h2.y * d2.y;
    }
    g_asrc[i] = s;
    g_adst[i] = d;
}

// ---------------- fused single-pass softmax-aggregate + mean + ELU --------
// one warp per destination node; edges contiguous in g_es[row[n]..row[n+1])
// w = exp(leaky(logit)) inline (no max; logits bounded, validated).
// 2-stage pipeline: idx+alpha prefetched 2 pairs ahead, feature rows 1 pair.
__device__ __forceinline__ void acc_edge(float w, uint4 u,
                                         float4& a0, float4& a1) {
    float2 f;
    f = __half22float2(*(__half2*)&u.x); a0.x = fmaf(w, f.x, a0.x); a0.y = fmaf(w, f.y, a0.y);
    f = __half22float2(*(__half2*)&u.y); a0.z = fmaf(w, f.x, a0.z); a0.w = fmaf(w, f.y, a0.w);
    f = __half22float2(*(__half2*)&u.z); a1.x = fmaf(w, f.x, a1.x); a1.y = fmaf(w, f.y, a1.y);
    f = __half22float2(*(__half2*)&u.w); a1.z = fmaf(w, f.x, a1.z); a1.w = fmaf(w, f.y, a1.w);
}

__global__ void __launch_bounds__(256) k_agg(const float* __restrict__ bias,
                                             float* __restrict__ outf) {
    int gw = (blockIdx.x * blockDim.x + threadIdx.x) >> 5;
    int lane = threadIdx.x & 31;
    if (gw >= NN) return;
    int n = gw;
    int beg = g_row[n], end = g_row[n + 1];
    int head = lane >> 3;
    float adh = __ldg(&g_adst[n * 4 + head]);

    float4 acc0 = {0.f, 0.f, 0.f, 0.f}, acc1 = {0.f, 0.f, 0.f, 0.f};
    float wsum = 0.f;
    const uint4* h16 = (const uint4*)g_hh;   // 8 halves per uint4; 32 per row

    int P = (end - beg) >> 1;                // number of full pairs

    // pipeline registers
    int   s0 = 0, s1 = 0;                    // pair p   indices (data loaded)
    float a0 = 0.f, a1 = 0.f;                //           alphas
    uint4 u0 = {0, 0, 0, 0}, u1 = {0, 0, 0, 0}; //        feature rows
    int   s2 = 0, s3 = 0;                    // pair p+1 indices (rows pending)
    float a2 = 0.f, a3 = 0.f;

    if (P >= 1) {
        s0 = g_es[beg];     s1 = g_es[beg + 1];
        a0 = __ldg(&g_asrc[s0 * 4 + head]);
        a1 = __ldg(&g_asrc[s1 * 4 + head]);
        if (P >= 2) {
            s2 = g_es[beg + 2]; s3 = g_es[beg + 3];
            a2 = __ldg(&g_asrc[s2 * 4 + head]);
            a3 = __ldg(&g_asrc[s3 * 4 + head]);
        }
        u0 = h16[(size_t)s0 * 32 + lane];
        u1 = h16[(size_t)s1 * 32 + lane];
    }

    for (int p = 0; p < P; p++) {
        // stage 1: feature rows for pair p+1 (indices already resolved)
        uint4 v0 = u0, v1 = u1;
        if (p + 1 < P) {
            v0 = h16[(size_t)s2 * 32 + lane];
            v1 = h16[(size_t)s3 * 32 + lane];
        }
        // stage 2: indices + alphas for pair p+2
        int t2 = 0, t3 = 0;
        float b2 = 0.f, b3 = 0.f;
        if (p + 2 < P) {
            int ii = beg + 2 * (p + 2);
            t2 = g_es[ii]; t3 = g_es[ii + 1];
            b2 = __ldg(&g_asrc[t2 * 4 + head]);
            b3 = __ldg(&g_asrc[t3 * 4 + head]);
        }
        // compute pair p (all operands loaded >= 1 iteration ago)
        float e0 = a0 + adh; e0 = (e0 >= 0.f) ? e0 : 0.2f * e0;
        float e1 = a1 + adh; e1 = (e1 >= 0.f) ? e1 : 0.2f * e1;
        float w0 = __expf(e0);
        float w1 = __expf(e1);
        wsum += w0 + w1;
        acc_edge(w0, u0, acc0, acc1);
        acc_edge(w1, u1, acc0, acc1);
        // rotate pipeline
        a0 = a2; a1 = a3; u0 = v0; u1 = v1;
        s2 = t2; s3 = t3; a2 = b2; a3 = b3;
    }

    int i = beg + P * 2;
    if (i < end) {                           // odd remaining edge
        int sz = g_es[i];
        float e0 = __ldg(&g_asrc[sz * 4 + head]) + adh;
        e0 = (e0 >= 0.f) ? e0 : 0.2f * e0;
        float w0 = __expf(e0);
        uint4 uz = h16[(size_t)sz * 32 + lane];
        wsum += w0;
        acc_edge(w0, uz, acc0, acc1);
    }

    float nrm = 1.f / wsum;
    acc0.x *= nrm; acc0.y *= nrm; acc0.z *= nrm; acc0.w *= nrm;
    acc1.x *= nrm; acc1.y *= nrm; acc1.z *= nrm; acc1.w *= nrm;

    // head sum across lanes {L, L^8, L^16, L^24} (head bits are lane bits 3,4)
#pragma unroll
    for (int o = 8; o <= 16; o <<= 1) {
        acc0.x += __shfl_xor_sync(0xffffffffu, acc0.x, o);
        acc0.y += __shfl_xor_sync(0xffffffffu, acc0.y, o);
        acc0.z += __shfl_xor_sync(0xffffffffu, acc0.z, o);
        acc0.w += __shfl_xor_sync(0xffffffffu, acc0.w, o);
        acc1.x += __shfl_xor_sync(0xffffffffu, acc1.x, o);
        acc1.y += __shfl_xor_sync(0xffffffffu, acc1.y, o);
        acc1.z += __shfl_xor_sync(0xffffffffu, acc1.z, o);
        acc1.w += __shfl_xor_sync(0xffffffffu, acc1.w, o);
    }

    if (lane < 8) {
        float4 b0 = *(const float4*)&bias[lane * 8];
        float4 b1 = *(const float4*)&bias[lane * 8 + 4];
        float v;
        float4 o0, o1;
        v = 0.25f * acc0.x + b0.x; o0.x = (v > 0.f) ? v : (__expf(v) - 1.f);
        v = 0.25f * acc0.y + b0.y; o0.y = (v > 0.f) ? v : (__expf(v) - 1.f);
        v = 0.25f * acc0.z + b0.z; o0.z = (v > 0.f) ? v : (__expf(v) - 1.f);
        v = 0.25f * acc0.w + b0.w; o0.w = (v > 0.f) ? v : (__expf(v) - 1.f);
        v = 0.25f * acc1.x + b1.x; o1.x = (v > 0.f) ? v : (__expf(v) - 1.f);
        v = 0.25f * acc1.y + b1.y; o1.y = (v > 0.f) ? v : (__expf(v) - 1.f);
        v = 0.25f * acc1.z + b1.z; o1.z = (v > 0.f) ? v : (__expf(v) - 1.f);
        v = 0.25f * acc1.w + b1.w; o1.w = (v > 0.f) ? v : (__expf(v) - 1.f);
        float4* op = (float4*)&outf[n * HID + lane * 8];
        op[0] = o0;
        op[1] = o1;
    }
}

// ---------------- scorer MLP: warp per node -------------------------------
__global__ void k_scorer(const float* __restrict__ feat, const float* __restrict__ donor,
                         const float* __restrict__ Ws1, const float* __restrict__ bs1,
                         const float* __restrict__ Ws2, const float* __restrict__ bs2,
                         float* __restrict__ out) {
    __shared__ float sW1[96 * 64];
    __shared__ float sW2[64];
    __shared__ float sB[64];
    __shared__ float sD[32];
    int t = threadIdx.x;
    for (int i = t; i < 96 * 64; i += 256) sW1[i] = Ws1[i];
    if (t < 64) { sW2[t] = Ws2[t]; sB[t] = bs1[t]; }
    if (t < 32) sD[t] = donor[t];
    __syncthreads();

    int warp = t >> 5, lane = t & 31;
    float b2v = bs2[0];
    for (int n = blockIdx.x * 8 + warp; n < NN; n += gridDim.x * 8) {
        float f0 = feat[n * 64 + lane];
        float f1 = feat[n * 64 + 32 + lane];
        float h0 = 0.f, h1 = 0.f;
#pragma unroll
        for (int k = 0; k < 32; k++) {
            float xk = __shfl_sync(0xffffffffu, f0, k);
            h0 = fmaf(xk, sW1[k * 64 + lane], h0);
            h1 = fmaf(xk, sW1[k * 64 + 32 + lane], h1);
        }
#pragma unroll
        for (int k = 0; k < 32; k++) {
            float xk = __shfl_sync(0xffffffffu, f1, k);
            h0 = fmaf(xk, sW1[(k + 32) * 64 + lane], h0);
            h1 = fmaf(xk, sW1[(k + 32) * 64 + 32 + lane], h1);
        }
#pragma unroll
        for (int k = 0; k < 32; k++) {
            float xk = sD[k];
            h0 = fmaf(xk, sW1[(k + 64) * 64 + lane], h0);
            h1 = fmaf(xk, sW1[(k + 64) * 64 + 32 + lane], h1);
        }
        h0 = fmaxf(h0 + sB[lane], 0.f);
        h1 = fmaxf(h1 + sB[lane + 32], 0.f);
        float p = h0 * sW2[lane] + h1 * sW2[lane + 32];
#pragma unroll
        for (int o = 16; o > 0; o >>= 1) p += __shfl_xor_sync(0xffffffffu, p, o);
        if (lane == 0) out[n] = p + b2v;
    }
}

// ---------------- launch (forked-stream capture: CSR || layer-1 gemm) -----
extern "C" void kernel_launch(void* const* d_in, const int* in_sizes, int n_in,
                              void* d_out, int out_size) {
    const float* x     = (const float*)d_in[0];
    const int*   ei    = (const int*)  d_in[1];
    const float* donor = (const float*)d_in[2];
    const float* W1    = (const float*)d_in[3];
    const float* as1   = (const float*)d_in[4];
    const float* ad1   = (const float*)d_in[5];
    const float* b1    = (const float*)d_in[6];
    const float* W2    = (const float*)d_in[7];
    const float* as2   = (const float*)d_in[8];
    const float* ad2   = (const float*)d_in[9];
    const float* b2    = (const float*)d_in[10];
    const float* Ws1   = (const float*)d_in[11];
    const float* bs1   = (const float*)d_in[12];
    const float* Ws2   = (const float*)d_in[13];
    const float* bs2   = (const float*)d_in[14];
    float* out = (float*)d_out;

    float *feat1, *feat2;
    cudaGetSymbolAddress((void**)&feat1, g_feat1);
    cudaGetSymbolAddress((void**)&feat2, g_feat2);

    const int smem27 = 27 * FOUT * 4 + 8 * 27 * 4;
    const int smem64 = 64 * FOUT * 4 + 8 * 64 * 4;
    cudaFuncSetAttribute(k_gemm<27>, cudaFuncAttributeMaxDynamicSharedMemorySize, smem27);
    cudaFuncSetAttribute(k_gemm<64>, cudaFuncAttributeMaxDynamicSharedMemorySize, smem64);

    const int alphaGrid = (NN * 4 + 255) / 256;
    const int edgeGrid  = (ETOT + 255) / 256;
    const int aggGrid   = (NN + 7) / 8;          // warp per node, 8 warps/block

    // fork a side stream for the CSR build (independent of layer-1 GEMM)
    cudaStream_t sCSR;
    cudaEvent_t evFork, evJoin;
    cudaStreamCreateWithFlags(&sCSR, cudaStreamNonBlocking);
    cudaEventCreateWithFlags(&evFork, cudaEventDisableTiming);
    cudaEventCreateWithFlags(&evJoin, cudaEventDisableTiming);

    cudaEventRecord(evFork, 0);
    cudaStreamWaitEvent(sCSR, evFork, 0);

    // ---- CSR build on side stream ----
    k_count<<<edgeGrid, 256, 0, sCSR>>>(ei);
    k_scan1<<<NBLK, 256, 0, sCSR>>>();
    k_scan23<<<NBLK, 256, 0, sCSR>>>();
    k_scatter<<<edgeGrid, 256, 0, sCSR>>>(ei);
    cudaEventRecord(evJoin, sCSR);

    // ---- layer-1 GEMM + alpha on main stream (parallel with CSR) ----
    k_gemm<27><<<1036, 256, smem27>>>(x, W1);
    k_alpha<<<alphaGrid, 256>>>(as1, ad1);

    // join: agg needs both CSR and alpha
    cudaStreamWaitEvent(0, evJoin, 0);
    k_agg<<<aggGrid, 256>>>(b1, feat1);

    // ---- layer 2 (serial chain) ----
    k_gemm<64><<<444, 256, smem64>>>(feat1, W2);
    k_alpha<<<alphaGrid, 256>>>(as2, ad2);
    k_agg<<<aggGrid, 256>>>(b2, feat2);

    // ---- scorer ----
    k_scorer<<<1184, 256>>>(feat2, donor, Ws1, bs1, Ws2, bs2, out);

    cudaStreamDestroy(sCSR);
    cudaEventDestroy(evFork);
    cudaEventDestroy(evJoin);
}

// round 14
// speedup vs baseline: 1.0465x; 1.0465x over previous
#include <cuda_runtime.h>
#include <cuda_fp16.h>

#define NN    50000
#define NE    800000
#define ETOT  (NE + NN)       // edges + self loops
#define FOUT  256             // HEADS * HIDDEN
#define HID   64
#define NPAD  50176           // 196 * 256
#define NBLK  196

// ---------------- scratch (device globals; no allocation allowed) ----------
__device__ __half g_hh[NN * FOUT];     // per-layer node features, fp16 [N, H*C]
__device__ float  g_asrc[NN * 4];
__device__ float  g_adst[NN * 4];
__device__ float  g_feat1[NN * HID];
__device__ float  g_feat2[NN * HID];

// CSR build (dst-sorted edges; built once per call, reused by both layers)
// g_cnt starts zero (static init) and is re-zeroed by k_scan23 each call.
__device__ int g_cnt[NPAD];
__device__ int g_incl[NPAD];
__device__ int g_bsum[NBLK];
__device__ int g_row[NN + 1];
__device__ int g_cur[NN];
__device__ int g_es[ETOT];             // src node ids grouped by dst

// ---------------- CSR build ------------------------------------------------
__global__ void k_count(const int* __restrict__ ei) {
    int e = blockIdx.x * blockDim.x + threadIdx.x;
    if (e >= ETOT) return;
    int dst = (e < NE) ? ei[NE + e] : (e - NE);
    atomicAdd(&g_cnt[dst], 1);
}

__global__ void k_scan1() {
    __shared__ int s[256];
    int t = threadIdx.x, i = blockIdx.x * 256 + t;
    int c = g_cnt[i];
    s[t] = c;
    __syncthreads();
#pragma unroll
    for (int off = 1; off < 256; off <<= 1) {
        int v = (t >= off) ? s[t - off] : 0;
        __syncthreads();
        s[t] += v;
        __syncthreads();
    }
    g_incl[i] = s[t];
    if (t == 255) g_bsum[blockIdx.x] = s[255];
}

// merged scan2+scan3: each block computes its own prefix offset from g_bsum,
// then finalizes row/cur for its 256 nodes and re-zeroes g_cnt.
__global__ void k_scan23() {
    __shared__ int s[256];
    int t = threadIdx.x;
    int b = blockIdx.x;
    s[t] = (t < b) ? g_bsum[t] : 0;    // sum of block-sums before block b
    __syncthreads();
#pragma unroll
    for (int off = 128; off > 0; off >>= 1) {
        if (t < off) s[t] += s[t + off];
        __syncthreads();
    }
    int boff = s[0];
    int i = b * 256 + t;
    int inc = g_incl[i] + boff;
    int c = g_cnt[i];
    if (i < NN) {
        g_row[i + 1] = inc;
        g_cur[i] = inc - c;
    }
    g_cnt[i] = 0;                      // ready for next call (replay-invariant)
    if (i == 0) g_row[0] = 0;
}

__global__ void k_scatter(const int* __restrict__ ei) {
    int e = blockIdx.x * blockDim.x + threadIdx.x;
    if (e >= ETOT) return;
    int src, dst;
    if (e < NE) { src = ei[e]; dst = ei[NE + e]; }
    else        { src = dst = e - NE; }
    int pos = atomicAdd(&g_cur[dst], 1);
    g_es[pos] = src;
}

// ---------------- feature GEMM: g_hh = fp16(X @ W)  (W: [FIN, 256]) -------
// register-prefetch double buffering: next tile's X loaded into regs during
// current tile's compute; inter-sync window is only a reg->smem store.
template <int FIN>
__global__ void k_gemm(const float* __restrict__ X, const float* __restrict__ W) {
    extern __shared__ float sm[];
    float* Wsh = sm;                 // [FIN][256]
    float* Xs  = sm + FIN * FOUT;    // [FIN][8]
    int t = threadIdx.x;

    for (int i = t; i < FIN * (FOUT / 4); i += 256)
        ((float4*)Wsh)[i] = ((const float4*)W)[i];

    const int nTiles = (NN + 7) / 8;
    const int NLD = (8 * FIN + 255) / 256;   // loads per thread per tile (<=2)
    float rv[2];

    int tile = blockIdx.x;
    if (tile < nTiles) {
        int n0 = tile * 8;
#pragma unroll
        for (int u = 0; u < NLD; u++) {
            int idx = t + u * 256;
            if (idx < 8 * FIN) {
                int k = idx >> 3, i = idx & 7;
                int n = n0 + i;
                rv[u] = (n < NN) ? X[n * FIN + k] : 0.f;
            }
        }
    }

    for (; tile < nTiles; tile += gridDim.x) {
        __syncthreads();   // protect Xs from previous compute / Wsh first iter
#pragma unroll
        for (int u = 0; u < NLD; u++) {
            int idx = t + u * 256;
            if (idx < 8 * FIN) Xs[idx] = rv[u];
        }
        __syncthreads();

        // prefetch next tile while computing this one
        int nx = tile + gridDim.x;
        if (nx < nTiles) {
            int n0 = nx * 8;
#pragma unroll
            for (int u = 0; u < NLD; u++) {
                int idx = t + u * 256;
                if (idx < 8 * FIN) {
                    int k = idx >> 3, i = idx & 7;
                    int n = n0 + i;
                    rv[u] = (n < NN) ? X[n * FIN + k] : 0.f;
                }
            }
        }

        float acc[8];
#pragma unroll
        for (int i = 0; i < 8; i++) acc[i] = 0.f;
#pragma unroll
        for (int k = 0; k < FIN; k++) {
            float  w  = Wsh[k * FOUT + t];
            float4 xa = *(const float4*)&Xs[k * 8];
            float4 xb = *(const float4*)&Xs[k * 8 + 4];
            acc[0] = fmaf(xa.x, w, acc[0]);
            acc[1] = fmaf(xa.y, w, acc[1]);
            acc[2] = fmaf(xa.z, w, acc[2]);
            acc[3] = fmaf(xa.w, w, acc[3]);
            acc[4] = fmaf(xb.x, w, acc[4]);
            acc[5] = fmaf(xb.y, w, acc[5]);
            acc[6] = fmaf(xb.z, w, acc[6]);
            acc[7] = fmaf(xb.w, w, acc[7]);
        }
        int n0 = tile * 8;
#pragma unroll
        for (int i = 0; i < 8; i++) {
            int n = n0 + i;
            if (n < NN) g_hh[n * FOUT + t] = __float2half_rn(acc[i]);
        }
    }
}

// ---------------- alpha_src / alpha_dst per (node, head) ------------------
__global__ void k_alpha(const float* __restrict__ a_src, const float* __restrict__ a_dst) {
    int i = blockIdx.x * blockDim.x + threadIdx.x;
    if (i >= NN * 4) return;
    int node = i >> 2, hd = i & 3;
    const __half2* hp = (const __half2*)&g_hh[node * FOUT + hd * HID];
    const float2*  ap = (const float2*)&a_src[hd * HID];
    const float2*  dp = (const float2*)&a_dst[hd * HID];
    float s = 0.f, d = 0.f;
#pragma unroll
    for (int j = 0; j < HID / 2; j++) {
        float2 h2 = __half22float2(hp[j]);
        float2 a2 = ap[j], d2 = dp[j];
        s += h2.x * a2.x + h2.y * a2.y;
        d += h2.x * d2.x + h2.y * d2.y;
    }
    g_asrc[i] = s;
    g_adst[i] = d;
}

// ---------------- fused single-pass softmax-aggregate + mean + ELU --------
// one warp per destination node; edges contiguous in g_es[row[n]..row[n+1])
// w = exp(leaky(logit)) computed inline (no max; logits bounded, validated);
// edge index AND its asrc value prefetched one iteration ahead (unroll-2).
// (R12 body — best measured configuration; do not restructure further.)
__device__ __forceinline__ void acc_edge(float w, uint4 u,
                                         float4& a0, float4& a1) {
    float2 f;
    f = __half22float2(*(__half2*)&u.x); a0.x = fmaf(w, f.x, a0.x); a0.y = fmaf(w, f.y, a0.y);
    f = __half22float2(*(__half2*)&u.y); a0.z = fmaf(w, f.x, a0.z); a0.w = fmaf(w, f.y, a0.w);
    f = __half22float2(*(__half2*)&u.z); a1.x = fmaf(w, f.x, a1.x); a1.y = fmaf(w, f.y, a1.y);
    f = __half22float2(*(__half2*)&u.w); a1.z = fmaf(w, f.x, a1.z); a1.w = fmaf(w, f.y, a1.w);
}

__global__ void __launch_bounds__(256) k_agg(const float* __restrict__ bias,
                                             float* __restrict__ outf) {
    int gw = (blockIdx.x * blockDim.x + threadIdx.x) >> 5;
    int lane = threadIdx.x & 31;
    if (gw >= NN) return;
    int n = gw;
    int beg = g_row[n], end = g_row[n + 1];
    int head = lane >> 3;
    float adh = __ldg(&g_adst[n * 4 + head]);

    float4 a0 = {0.f, 0.f, 0.f, 0.f}, a1 = {0.f, 0.f, 0.f, 0.f};
    float wsum = 0.f;
    const uint4* h16 = (const uint4*)g_hh;   // 8 halves per uint4; 32 per row
    int i = beg;
    int sA = 0, sB = 0;
    float aA = 0.f, aB = 0.f;
    if (i + 2 <= end) {
        sA = g_es[i]; sB = g_es[i + 1];
        aA = __ldg(&g_asrc[sA * 4 + head]);
        aB = __ldg(&g_asrc[sB * 4 + head]);
    }
    while (i + 2 <= end) {
        uint4 u0 = h16[(size_t)sA * 32 + lane];
        uint4 u1 = h16[(size_t)sB * 32 + lane];
        float e0 = aA + adh; e0 = (e0 >= 0.f) ? e0 : 0.2f * e0;
        float e1 = aB + adh; e1 = (e1 >= 0.f) ? e1 : 0.2f * e1;
        float w0 = __expf(e0);
        float w1 = __expf(e1);
        int j = i + 2;
        if (j + 2 <= end) {
            sA = g_es[j]; sB = g_es[j + 1];
            aA = __ldg(&g_asrc[sA * 4 + head]);
            aB = __ldg(&g_asrc[sB * 4 + head]);
        }
        wsum += w0 + w1;
        acc_edge(w0, u0, a0, a1);
        acc_edge(w1, u1, a0, a1);
        i = j;
    }
    if (i < end) {
        int s0 = g_es[i];
        float e0 = __ldg(&g_asrc[s0 * 4 + head]) + adh;
        e0 = (e0 >= 0.f) ? e0 : 0.2f * e0;
        float w0 = __expf(e0);
        uint4 u0 = h16[(size_t)s0 * 32 + lane];
        wsum += w0;
        acc_edge(w0, u0, a0, a1);
    }

    float nrm = 1.f / wsum;
    a0.x *= nrm; a0.y *= nrm; a0.z *= nrm; a0.w *= nrm;
    a1.x *= nrm; a1.y *= nrm; a1.z *= nrm; a1.w *= nrm;

    // head sum across lanes {L, L^8, L^16, L^24} (head bits are lane bits 3,4)
#pragma unroll
    for (int o = 8; o <= 16; o <<= 1) {
        a0.x += __shfl_xor_sync(0xffffffffu, a0.x, o);
        a0.y += __shfl_xor_sync(0xffffffffu, a0.y, o);
        a0.z += __shfl_xor_sync(0xffffffffu, a0.z, o);
        a0.w += __shfl_xor_sync(0xffffffffu, a0.w, o);
        a1.x += __shfl_xor_sync(0xffffffffu, a1.x, o);
        a1.y += __shfl_xor_sync(0xffffffffu, a1.y, o);
        a1.z += __shfl_xor_sync(0xffffffffu, a1.z, o);
        a1.w += __shfl_xor_sync(0xffffffffu, a1.w, o);
    }

    if (lane < 8) {
        float4 b0 = *(const float4*)&bias[lane * 8];
        float4 b1 = *(const float4*)&bias[lane * 8 + 4];
        float v;
        float4 o0, o1;
        v = 0.25f * a0.x + b0.x; o0.x = (v > 0.f) ? v : (__expf(v) - 1.f);
        v = 0.25f * a0.y + b0.y; o0.y = (v > 0.f) ? v : (__expf(v) - 1.f);
        v = 0.25f * a0.z + b0.z; o0.z = (v > 0.f) ? v : (__expf(v) - 1.f);
        v = 0.25f * a0.w + b0.w; o0.w = (v > 0.f) ? v : (__expf(v) - 1.f);
        v = 0.25f * a1.x + b1.x; o1.x = (v > 0.f) ? v : (__expf(v) - 1.f);
        v = 0.25f * a1.y + b1.y; o1.y = (v > 0.f) ? v : (__expf(v) - 1.f);
        v = 0.25f * a1.z + b1.z; o1.z = (v > 0.f) ? v : (__expf(v) - 1.f);
        v = 0.25f * a1.w + b1.w; o1.w = (v > 0.f) ? v : (__expf(v) - 1.f);
        float4* op = (float4*)&outf[n * HID + lane * 8];
        op[0] = o0;
        op[1] = o1;
    }
}

// ---------------- scorer MLP: warp per node -------------------------------
__global__ void k_scorer(const float* __restrict__ feat, const float* __restrict__ donor,
                         const float* __restrict__ Ws1, const float* __restrict__ bs1,
                         const float* __restrict__ Ws2, const float* __restrict__ bs2,
                         float* __restrict__ out) {
    __shared__ float sW1[96 * 64];
    __shared__ float sW2[64];
    __shared__ float sB[64];
    __shared__ float sD[32];
    int t = threadIdx.x;
    for (int i = t; i < 96 * 64; i += 256) sW1[i] = Ws1[i];
    if (t < 64) { sW2[t] = Ws2[t]; sB[t] = bs1[t]; }
    if (t < 32) sD[t] = donor[t];
    __syncthreads();

    int warp = t >> 5, lane = t & 31;
    float b2v = bs2[0];
    for (int n = blockIdx.x * 8 + warp; n < NN; n += gridDim.x * 8) {
        float f0 = feat[n * 64 + lane];
        float f1 = feat[n * 64 + 32 + lane];
        float h0 = 0.f, h1 = 0.f;
#pragma unroll
        for (int k = 0; k < 32; k++) {
            float xk = __shfl_sync(0xffffffffu, f0, k);
            h0 = fmaf(xk, sW1[k * 64 + lane], h0);
            h1 = fmaf(xk, sW1[k * 64 + 32 + lane], h1);
        }
#pragma unroll
        for (int k = 0; k < 32; k++) {
            float xk = __shfl_sync(0xffffffffu, f1, k);
            h0 = fmaf(xk, sW1[(k + 32) * 64 + lane], h0);
            h1 = fmaf(xk, sW1[(k + 32) * 64 + 32 + lane], h1);
        }
#pragma unroll
        for (int k = 0; k < 32; k++) {
            float xk = sD[k];
            h0 = fmaf(xk, sW1[(k + 64) * 64 + lane], h0);
            h1 = fmaf(xk, sW1[(k + 64) * 64 + 32 + lane], h1);
        }
        h0 = fmaxf(h0 + sB[lane], 0.f);
        h1 = fmaxf(h1 + sB[lane + 32], 0.f);
        float p = h0 * sW2[lane] + h1 * sW2[lane + 32];
#pragma unroll
        for (int o = 16; o > 0; o >>= 1) p += __shfl_xor_sync(0xffffffffu, p, o);
        if (lane == 0) out[n] = p + b2v;
    }
}

// ---------------- launch (forked-stream capture: CSR || layer-1 gemm) -----
extern "C" void kernel_launch(void* const* d_in, const int* in_sizes, int n_in,
                              void* d_out, int out_size) {
    const float* x     = (const float*)d_in[0];
    const int*   ei    = (const int*)  d_in[1];
    const float* donor = (const float*)d_in[2];
    const float* W1    = (const float*)d_in[3];
    const float* as1   = (const float*)d_in[4];
    const float* ad1   = (const float*)d_in[5];
    const float* b1    = (const float*)d_in[6];
    const float* W2    = (const float*)d_in[7];
    const float* as2   = (const float*)d_in[8];
    const float* ad2   = (const float*)d_in[9];
    const float* b2    = (const float*)d_in[10];
    const float* Ws1   = (const float*)d_in[11];
    const float* bs1   = (const float*)d_in[12];
    const float* Ws2   = (const float*)d_in[13];
    const float* bs2   = (const float*)d_in[14];
    float* out = (float*)d_out;

    float *feat1, *feat2;
    cudaGetSymbolAddress((void**)&feat1, g_feat1);
    cudaGetSymbolAddress((void**)&feat2, g_feat2);

    const int smem27 = 27 * FOUT * 4 + 8 * 27 * 4;
    const int smem64 = 64 * FOUT * 4 + 8 * 64 * 4;
    cudaFuncSetAttribute(k_gemm<27>, cudaFuncAttributeMaxDynamicSharedMemorySize, smem27);
    cudaFuncSetAttribute(k_gemm<64>, cudaFuncAttributeMaxDynamicSharedMemorySize, smem64);

    const int alphaGrid = (NN * 4 + 255) / 256;
    const int edgeGrid  = (ETOT + 255) / 256;
    const int aggGrid   = (NN + 7) / 8;          // warp per node, 8 warps/block

    // fork a side stream for the CSR build (independent of layer-1 GEMM)
    cudaStream_t sCSR;
    cudaEvent_t evFork, evJoin;
    cudaStreamCreateWithFlags(&sCSR, cudaStreamNonBlocking);
    cudaEventCreateWithFlags(&evFork, cudaEventDisableTiming);
    cudaEventCreateWithFlags(&evJoin, cudaEventDisableTiming);

    cudaEventRecord(evFork, 0);
    cudaStreamWaitEvent(sCSR, evFork, 0);

    // ---- CSR build on side stream ----
    k_count<<<edgeGrid, 256, 0, sCSR>>>(ei);
    k_scan1<<<NBLK, 256, 0, sCSR>>>();
    k_scan23<<<NBLK, 256, 0, sCSR>>>();
    k_scatter<<<edgeGrid, 256, 0, sCSR>>>(ei);
    cudaEventRecord(evJoin, sCSR);

    // ---- layer-1 GEMM + alpha on main stream (parallel with CSR) ----
    k_gemm<27><<<1036, 256, smem27>>>(x, W1);
    k_alpha<<<alphaGrid, 256>>>(as1, ad1);

    // join: agg needs both CSR and alpha
    cudaStreamWaitEvent(0, evJoin, 0);
    k_agg<<<aggGrid, 256>>>(b1, feat1);

    // ---- layer 2 (serial chain) ----
    k_gemm<64><<<444, 256, smem64>>>(feat1, W2);
    k_alpha<<<alphaGrid, 256>>>(as2, ad2);
    k_agg<<<aggGrid, 256>>>(b2, feat2);

    // ---- scorer ----
    k_scorer<<<1184, 256>>>(feat2, donor, Ws1, bs1, Ws2, bs2, out);

    cudaStreamDestroy(sCSR);
    cudaEventDestroy(evFork);
    cudaEventDestroy(evJoin);
}